// round 2
// baseline (speedup 1.0000x reference)
#include <cuda_runtime.h>
#include <math.h>

#define BN 8192
#define DD 512
#define MARGIN 0.3f

// -------- device scratch (no allocations allowed) --------
__device__ float g_fn[(size_t)BN * DD];        // normalized features (16 MB)
__device__ float g_sq[BN];                     // ||f_i||^2 after normalize
__device__ int   g_lab[BN];                    // labels as int32
__device__ float g_dist[(size_t)BN * BN];      // pairwise distances (256 MB)
__device__ float g_rowval[BN];                 // per-anchor loss contribution
__device__ int   g_rowcnt[BN];                 // per-anchor contrib flag

// ---------------- labels int64 -> int32 ----------------
__global__ void k_labels(const long long* __restrict__ lab) {
    int i = blockIdx.x * blockDim.x + threadIdx.x;
    if (i < BN) g_lab[i] = (int)lab[i];
}

// ---------------- row L2 normalize ----------------
// one block of 128 threads per row; each thread owns one float4 (D=512)
__global__ void k_norm(const float* __restrict__ X) {
    int row = blockIdx.x;
    int t = threadIdx.x;
    const float4* xr = (const float4*)(X + (size_t)row * DD);
    float4 v = xr[t];
    float ss = v.x * v.x + v.y * v.y + v.z * v.z + v.w * v.w;
    // warp reduce
    #pragma unroll
    for (int off = 16; off > 0; off >>= 1)
        ss += __shfl_xor_sync(0xffffffffu, ss, off);
    __shared__ float ws[4];
    if ((t & 31) == 0) ws[t >> 5] = ss;
    __syncthreads();
    float tot = ws[0] + ws[1] + ws[2] + ws[3];
    float nrm = sqrtf(tot);
    float den = fmaxf(nrm, 1e-12f);
    float s = 1.0f / den;
    v.x *= s; v.y *= s; v.z *= s; v.w *= s;
    ((float4*)(g_fn + (size_t)row * DD))[t] = v;
    if (t == 0) g_sq[row] = tot * s * s;   // ||normalized row||^2
}

// ---------------- pairwise distance GEMM ----------------
// C[i][j] = sqrt(max(sq_i + sq_j - 2 * dot(f_i, f_j), 0))
// 128x128 block tile, BK=8, 256 threads, 8x8 per thread.
__global__ __launch_bounds__(256) void k_gemm() {
    __shared__ float As[8][132];   // padded: conflict-free stores + aligned LDS.128
    __shared__ float Bs[8][132];

    int tid  = threadIdx.x;
    int row0 = blockIdx.y * 128;
    int col0 = blockIdx.x * 128;

    float acc[8][8];
    #pragma unroll
    for (int r = 0; r < 8; r++)
        #pragma unroll
        for (int c = 0; c < 8; c++) acc[r][c] = 0.0f;

    int lr = tid >> 1;          // 0..127 : row within tile for loading
    int lk = (tid & 1) * 4;     // 0 or 4 : k offset for loading

    const float* Aptr = g_fn + (size_t)(row0 + lr) * DD + lk;
    const float* Bptr = g_fn + (size_t)(col0 + lr) * DD + lk;

    int tx = tid & 15;          // 0..15 column group
    int ty = tid >> 4;          // 0..15 row group

    for (int kt = 0; kt < DD; kt += 8) {
        float4 va = *(const float4*)(Aptr + kt);
        float4 vb = *(const float4*)(Bptr + kt);
        __syncthreads();
        As[lk + 0][lr] = va.x; As[lk + 1][lr] = va.y;
        As[lk + 2][lr] = va.z; As[lk + 3][lr] = va.w;
        Bs[lk + 0][lr] = vb.x; Bs[lk + 1][lr] = vb.y;
        Bs[lk + 2][lr] = vb.z; Bs[lk + 3][lr] = vb.w;
        __syncthreads();

        #pragma unroll
        for (int kk = 0; kk < 8; kk++) {
            float ar[8], br[8];
            *(float4*)(ar)     = *(const float4*)&As[kk][ty * 8];
            *(float4*)(ar + 4) = *(const float4*)&As[kk][ty * 8 + 4];
            *(float4*)(br)     = *(const float4*)&Bs[kk][tx * 8];
            *(float4*)(br + 4) = *(const float4*)&Bs[kk][tx * 8 + 4];
            #pragma unroll
            for (int r = 0; r < 8; r++)
                #pragma unroll
                for (int c = 0; c < 8; c++)
                    acc[r][c] = fmaf(ar[r], br[c], acc[r][c]);
        }
    }

    float sqa[8], sqb[8];
    #pragma unroll
    for (int r = 0; r < 8; r++) sqa[r] = g_sq[row0 + ty * 8 + r];
    #pragma unroll
    for (int c = 0; c < 8; c++) sqb[c] = g_sq[col0 + tx * 8 + c];

    #pragma unroll
    for (int r = 0; r < 8; r++) {
        float o[8];
        #pragma unroll
        for (int c = 0; c < 8; c++) {
            float d2 = sqa[r] + sqb[c] - 2.0f * acc[r][c];
            o[c] = sqrtf(fmaxf(d2, 0.0f));
        }
        float* dst = g_dist + (size_t)(row0 + ty * 8 + r) * BN + col0 + tx * 8;
        *(float4*)(dst)     = make_float4(o[0], o[1], o[2], o[3]);
        *(float4*)(dst + 4) = make_float4(o[4], o[5], o[6], o[7]);
    }
}

// ---------------- per-anchor semi-hard stats ----------------
// one block (256 threads) per anchor row; each thread handles 32 columns.
__global__ __launch_bounds__(256) void k_stats() {
    int i = blockIdx.x;
    int tid = threadIdx.x;
    const float* drow = g_dist + (size_t)i * BN;
    int li = g_lab[i];

    float d[32];
    unsigned match = 0;   // bit c -> labels equal for column j = tid + 256*c
    float psum = 0.0f;
    int   pcnt = 0;

    #pragma unroll
    for (int c = 0; c < 32; c++) {
        int j = tid + (c << 8);
        float dv = (j == i) ? 0.0f : drow[j];    // force exact-zero diagonal
        d[c] = dv;
        int lj = g_lab[j];
        if (lj == li) {
            match |= (1u << c);
            psum += dv;
            pcnt += 1;
        }
    }

    // block reduce psum / pcnt
    #pragma unroll
    for (int off = 16; off > 0; off >>= 1) {
        psum += __shfl_xor_sync(0xffffffffu, psum, off);
        pcnt += __shfl_xor_sync(0xffffffffu, pcnt, off);
    }
    __shared__ float ws[8];
    __shared__ int   wc[8];
    __shared__ float s_mean;
    __shared__ int   s_pcnt;
    int warp = tid >> 5;
    if ((tid & 31) == 0) { ws[warp] = psum; wc[warp] = pcnt; }
    __syncthreads();
    if (tid == 0) {
        float ts = 0.0f; int tc = 0;
        #pragma unroll
        for (int w = 0; w < 8; w++) { ts += ws[w]; tc += wc[w]; }
        s_pcnt = tc;
        s_mean = ts / (float)tc;   // tc >= 1 (self always matches)
    }
    __syncthreads();
    float mean = s_mean;
    int   pc   = s_pcnt;

    // min over semi-hard negatives: !match && d > mean
    float mn = 3.4e38f;
    #pragma unroll
    for (int c = 0; c < 32; c++) {
        bool neg = ((match >> c) & 1u) == 0u;
        if (neg && d[c] > mean) mn = fminf(mn, d[c]);
    }
    #pragma unroll
    for (int off = 16; off > 0; off >>= 1)
        mn = fminf(mn, __shfl_xor_sync(0xffffffffu, mn, off));
    if ((tid & 31) == 0) ws[warp] = mn;
    __syncthreads();
    if (tid == 0) {
        float m = 3.4e38f;
        #pragma unroll
        for (int w = 0; w < 8; w++) m = fminf(m, ws[w]);
        bool valid  = (pc > 1) && (pc < BN);
        bool has_sh = (m < 1e37f);
        bool contrib = valid && has_sh;
        float per = fmaxf(mean - m + MARGIN, 0.0f);
        g_rowval[i] = contrib ? per : 0.0f;
        g_rowcnt[i] = contrib ? 1 : 0;
    }
}

// ---------------- deterministic final reduction ----------------
__global__ void k_final(float* __restrict__ out) {
    int t = threadIdx.x;   // 256
    float s = 0.0f;
    int   c = 0;
    for (int j = t; j < BN; j += 256) { s += g_rowval[j]; c += g_rowcnt[j]; }
    #pragma unroll
    for (int off = 16; off > 0; off >>= 1) {
        s += __shfl_xor_sync(0xffffffffu, s, off);
        c += __shfl_xor_sync(0xffffffffu, c, off);
    }
    __shared__ float ws[8];
    __shared__ int   wc[8];
    int warp = t >> 5;
    if ((t & 31) == 0) { ws[warp] = s; wc[warp] = c; }
    __syncthreads();
    if (t == 0) {
        float ts = 0.0f; int tc = 0;
        #pragma unroll
        for (int w = 0; w < 8; w++) { ts += ws[w]; tc += wc[w]; }
        out[0] = (tc > 0) ? ts / (float)tc : 0.0f;
    }
}

extern "C" void kernel_launch(void* const* d_in, const int* in_sizes, int n_in,
                              void* d_out, int out_size) {
    const float*     X   = (const float*)d_in[0];
    const long long* lab = (const long long*)d_in[1];
    float*           out = (float*)d_out;

    k_labels<<<(BN + 255) / 256, 256>>>(lab);
    k_norm<<<BN, 128>>>(X);
    dim3 grid(BN / 128, BN / 128);
    k_gemm<<<grid, 256>>>();
    k_stats<<<BN, 256>>>();
    k_final<<<1, 256>>>(out);
}